// round 1
// baseline (speedup 1.0000x reference)
#include <cuda_runtime.h>

#define B_   2
#define N_   2048
#define DIM_ 1024
#define H_   16
#define D_   64

// Scratch (device globals: allocation-free rule)
__device__ float g_qT[(size_t)B_ * H_ * D_ * N_];   // [b][h][d][i], pre-transposed
__device__ float g_kT[(size_t)B_ * H_ * D_ * N_];   // [b][h][d][j]
__device__ float g_v [(size_t)B_ * H_ * N_ * D_];   // [b][h][j][d]
__device__ float g_attn[(size_t)B_ * N_ * DIM_];    // [b][i][h*64+d]

// ---------------------------------------------------------------------------
// Tiled fp32 GEMM: C[M,NB] = A[M,1024] * Bm[1024,NB]; 64x64 tile, 256 thr, 4x4
// mode 0: A=features, write qkv permuted into g_qT/g_kT/g_v
// mode 1: A=g_attn,   write plain into Cout
// ---------------------------------------------------------------------------
__global__ __launch_bounds__(256) void gemm64(const float* __restrict__ A,
                                              const float* __restrict__ Bm,
                                              float* __restrict__ Cout,
                                              int NB, int mode) {
    __shared__ float AsT[16 * 64];
    __shared__ float Bs[16 * 64];
    const int tid = threadIdx.x;
    const int ty = tid >> 4, tx = tid & 15;
    const int m0 = blockIdx.y * 64;
    const int n0 = blockIdx.x * 64;
    const float* Ap = (mode == 0) ? A : g_attn;
    const int K = 1024;

    const int ar = tid >> 2;          // 0..63
    const int ak = (tid & 3) * 4;     // 0,4,8,12
    const int bk = tid >> 4;          // 0..15
    const int bc = (tid & 15) * 4;    // 0..60

    float acc[4][4] = {};

    for (int k0 = 0; k0 < K; k0 += 16) {
        float4 av = *reinterpret_cast<const float4*>(&Ap[(size_t)(m0 + ar) * K + k0 + ak]);
        AsT[(ak + 0) * 64 + ar] = av.x;
        AsT[(ak + 1) * 64 + ar] = av.y;
        AsT[(ak + 2) * 64 + ar] = av.z;
        AsT[(ak + 3) * 64 + ar] = av.w;
        *reinterpret_cast<float4*>(&Bs[bk * 64 + bc]) =
            *reinterpret_cast<const float4*>(&Bm[(size_t)(k0 + bk) * NB + n0 + bc]);
        __syncthreads();
#pragma unroll
        for (int kk = 0; kk < 16; kk++) {
            float4 a4 = *reinterpret_cast<const float4*>(&AsT[kk * 64 + ty * 4]);
            float4 b4 = *reinterpret_cast<const float4*>(&Bs[kk * 64 + tx * 4]);
            float avv[4] = {a4.x, a4.y, a4.z, a4.w};
            float bvv[4] = {b4.x, b4.y, b4.z, b4.w};
#pragma unroll
            for (int ii = 0; ii < 4; ii++)
#pragma unroll
                for (int jj = 0; jj < 4; jj++) acc[ii][jj] += avv[ii] * bvv[jj];
        }
        __syncthreads();
    }

    if (mode == 0) {
        const int part = n0 >> 10;              // 0=q, 1=k, 2=v
        const int h = (n0 & 1023) >> 6;         // whole block maps to one head
        const int b = m0 >> 11;
        if (part < 2) {
            float* dst = (part == 0) ? g_qT : g_kT;
            const size_t base = (size_t)(b * H_ + h) * D_ * N_;
#pragma unroll
            for (int ii = 0; ii < 4; ii++) {
                const int i = (m0 + ty * 4 + ii) & (N_ - 1);
#pragma unroll
                for (int jj = 0; jj < 4; jj++)
                    dst[base + (size_t)(tx * 4 + jj) * N_ + i] = acc[ii][jj];
            }
        } else {
            const size_t base = (size_t)(b * H_ + h) * N_ * D_;
#pragma unroll
            for (int ii = 0; ii < 4; ii++) {
                const int i = (m0 + ty * 4 + ii) & (N_ - 1);
                *reinterpret_cast<float4*>(&g_v[base + (size_t)i * D_ + tx * 4]) =
                    make_float4(acc[ii][0], acc[ii][1], acc[ii][2], acc[ii][3]);
            }
        }
    } else {
#pragma unroll
        for (int ii = 0; ii < 4; ii++) {
            const int m = m0 + ty * 4 + ii;
            *reinterpret_cast<float4*>(&Cout[(size_t)m * NB + n0 + tx * 4]) =
                make_float4(acc[ii][0], acc[ii][1], acc[ii][2], acc[ii][3]);
        }
    }
}

// ---------------------------------------------------------------------------
// Fused segment attention. One block = 64 query rows of one (b,h).
// Pass 1: per-(row,seg) denominators of exp(qk/32) in registers -> smem.
// Pass 2: w = e * inv_denom[row][mask], O += w @ V.
// ---------------------------------------------------------------------------
__global__ __launch_bounds__(256) void attn_kernel(const int* __restrict__ mask) {
    extern __shared__ float sm[];
    float* qsT  = sm;            // [d][r] 64x64
    float* ksT  = sm + 4096;     // [d][c] 64x64, reused as ws[r][c] in pass 2
    float* vs   = sm + 8192;     // [j][d] 64x64
    float* dsh  = sm + 12288;    // [r][s] 64x4
    float* invd = sm + 12544;    // [r][s] 64x4

    const int b = blockIdx.z, h = blockIdx.y;
    const int i0 = blockIdx.x * 64;
    const int tid = threadIdx.x;
    const int ty = tid >> 4, tx = tid & 15;

    const size_t tb = (size_t)(b * H_ + h) * D_ * N_;   // base for qT / kT
    const float* vbase = g_v + (size_t)(b * H_ + h) * N_ * D_;
    const int* mrow = mask + (size_t)b * N_ * N_ + (size_t)i0 * N_;

    // load Q tile (pre-scaled by 1/32 — exact, power of 2)
    const float SC = 1.0f / 32.0f;
    for (int t = tid; t < 1024; t += 256) {
        const int d = t >> 4, rb = (t & 15) * 4;
        float4 qv = *reinterpret_cast<const float4*>(&g_qT[tb + (size_t)d * N_ + i0 + rb]);
        qv.x *= SC; qv.y *= SC; qv.z *= SC; qv.w *= SC;
        *reinterpret_cast<float4*>(&qsT[d * 64 + rb]) = qv;
    }
    dsh[tid] = 0.0f;
    __syncthreads();

    float dsum[4][4] = {};   // [row_ii][seg]

#define SCORES(S)                                                              \
    {                                                                          \
        _Pragma("unroll 8") for (int d = 0; d < 64; d++) {                     \
            float4 a4 = *reinterpret_cast<const float4*>(&qsT[d * 64 + ty * 4]); \
            float4 b4 = *reinterpret_cast<const float4*>(&ksT[d * 64 + tx * 4]); \
            float avv[4] = {a4.x, a4.y, a4.z, a4.w};                           \
            float bvv[4] = {b4.x, b4.y, b4.z, b4.w};                           \
            _Pragma("unroll") for (int ii = 0; ii < 4; ii++)                   \
                _Pragma("unroll") for (int jj = 0; jj < 4; jj++)               \
                    S[ii][jj] += avv[ii] * bvv[jj];                            \
        }                                                                      \
    }

#define LOAD_KT(j0)                                                            \
    for (int t = tid; t < 1024; t += 256) {                                    \
        const int d = t >> 4, cb = (t & 15) * 4;                               \
        *reinterpret_cast<float4*>(&ksT[d * 64 + cb]) =                        \
            *reinterpret_cast<const float4*>(&g_kT[tb + (size_t)d * N_ + (j0) + cb]); \
    }

    // ---------------- PASS 1: denominators ----------------
    for (int j0 = 0; j0 < N_; j0 += 64) {
        LOAD_KT(j0);
        __syncthreads();
        float s[4][4] = {};
        SCORES(s);
#pragma unroll
        for (int ii = 0; ii < 4; ii++) {
            const int4 mm = *reinterpret_cast<const int4*>(
                &mrow[(size_t)(ty * 4 + ii) * N_ + j0 + tx * 4]);
            float e0 = __expf(s[ii][0]), e1 = __expf(s[ii][1]);
            float e2 = __expf(s[ii][2]), e3 = __expf(s[ii][3]);
#define ACC1(SG, E)                                                            \
            if ((SG) == 0) dsum[ii][0] += (E);                                 \
            else if ((SG) == 1) dsum[ii][1] += (E);                            \
            else if ((SG) == 2) dsum[ii][2] += (E);                            \
            else dsum[ii][3] += (E);
            ACC1(mm.x, e0) ACC1(mm.y, e1) ACC1(mm.z, e2) ACC1(mm.w, e3)
#undef ACC1
        }
        __syncthreads();
    }
#pragma unroll
    for (int ii = 0; ii < 4; ii++)
#pragma unroll
        for (int ss = 0; ss < 4; ss++)
            atomicAdd(&dsh[(ty * 4 + ii) * 4 + ss], dsum[ii][ss]);
    __syncthreads();
    {
        const float dv = dsh[tid];
        invd[tid] = (dv == 0.0f) ? 1.0f : 1.0f / dv;   // matches where(s==0,1,s)
    }
    __syncthreads();

    // ---------------- PASS 2: O = w @ V ----------------
    float o[4][4] = {};
    for (int j0 = 0; j0 < N_; j0 += 64) {
        LOAD_KT(j0);
        const float4* vsrc = reinterpret_cast<const float4*>(vbase + (size_t)j0 * D_);
        for (int t = tid; t < 1024; t += 256)
            reinterpret_cast<float4*>(vs)[t] = vsrc[t];
        __syncthreads();
        float s[4][4] = {};
        SCORES(s);
        __syncthreads();   // all threads done reading ksT before overwrite
#pragma unroll
        for (int ii = 0; ii < 4; ii++) {
            const int r = ty * 4 + ii;
            const int4 mm = *reinterpret_cast<const int4*>(
                &mrow[(size_t)r * N_ + j0 + tx * 4]);
            const float w0 = __expf(s[ii][0]) * invd[r * 4 + mm.x];
            const float w1 = __expf(s[ii][1]) * invd[r * 4 + mm.y];
            const float w2 = __expf(s[ii][2]) * invd[r * 4 + mm.z];
            const float w3 = __expf(s[ii][3]) * invd[r * 4 + mm.w];
            *reinterpret_cast<float4*>(&ksT[r * 64 + tx * 4]) =
                make_float4(w0, w1, w2, w3);
        }
        __syncthreads();
#pragma unroll 4
        for (int j = 0; j < 64; j++) {
            const float4 vv = *reinterpret_cast<const float4*>(&vs[j * 64 + tx * 4]);
            const float w0 = ksT[(ty * 4 + 0) * 64 + j];
            const float w1 = ksT[(ty * 4 + 1) * 64 + j];
            const float w2 = ksT[(ty * 4 + 2) * 64 + j];
            const float w3 = ksT[(ty * 4 + 3) * 64 + j];
            o[0][0] += w0 * vv.x; o[0][1] += w0 * vv.y; o[0][2] += w0 * vv.z; o[0][3] += w0 * vv.w;
            o[1][0] += w1 * vv.x; o[1][1] += w1 * vv.y; o[1][2] += w1 * vv.z; o[1][3] += w1 * vv.w;
            o[2][0] += w2 * vv.x; o[2][1] += w2 * vv.y; o[2][2] += w2 * vv.z; o[2][3] += w2 * vv.w;
            o[3][0] += w3 * vv.x; o[3][1] += w3 * vv.y; o[3][2] += w3 * vv.z; o[3][3] += w3 * vv.w;
        }
        __syncthreads();
    }
#pragma unroll
    for (int ii = 0; ii < 4; ii++) {
        const int i = i0 + ty * 4 + ii;
        *reinterpret_cast<float4*>(
            &g_attn[(size_t)(b * N_ + i) * DIM_ + h * D_ + tx * 4]) =
            make_float4(o[ii][0], o[ii][1], o[ii][2], o[ii][3]);
    }
#undef SCORES
#undef LOAD_KT
}

// ---------------------------------------------------------------------------
extern "C" void kernel_launch(void* const* d_in, const int* in_sizes, int n_in,
                              void* d_out, int out_size) {
    const float* features = (const float*)d_in[0];
    const int*   mask     = (const int*)d_in[1];
    const float* W_qkv    = (const float*)d_in[2];
    const float* W_out    = (const float*)d_in[3];
    float* out = (float*)d_out;

    cudaFuncSetAttribute(attn_kernel, cudaFuncAttributeMaxDynamicSharedMemorySize,
                         51200);

    // qkv = features @ W_qkv  (permuted store into g_qT/g_kT/g_v)
    gemm64<<<dim3(3072 / 64, (B_ * N_) / 64), 256>>>(features, W_qkv, nullptr, 3072, 0);
    // fused masked-segment attention -> g_attn
    attn_kernel<<<dim3(N_ / 64, H_, B_), 256, 51200>>>(mask);
    // out = g_attn @ W_out
    gemm64<<<dim3(DIM_ / 64, (B_ * N_) / 64), 256>>>(nullptr, W_out, out, DIM_, 1);
}